// round 14
// baseline (speedup 1.0000x reference)
#include <cuda_runtime.h>
#include <math.h>

#define EPS 1e-7f

// B=32, S=2048, D=1024
#define B_ 32
#define S_ 2048
#define D_ 1024

#define KS 16                 // proj k-slices
#define DHH 64                // d-elements per slice
#define ET 32                 // e-tile per block
#define BT 16                 // b-tile per block (B split in 2)

__device__ float g_proj[B_][D_];   // merged proj (atomicAdd; zeroed by norm for next replay)
__device__ float g_sums[B_];       // per-batch sum of a

// ---------------------------------------------------------------------------
// Kernel 1: smem-tiled GEMM, b-split for occupancy.
// grid (32 e-tiles, 16 k-slices, 2 b-halves) = 1024 blocks (6.9/SM), 256 thr.
// Block: [32e x 16b] tile over 64-d slice. Thread: e = t&31, 2 batches
// (bg = t>>5 -> b = bg*2, bg*2+1). Ms padded [32][65] -> conflict-free scalar
// reads; Ys reads warp-uniform float4 broadcasts. 2 coalesced REDs/thread.
// ---------------------------------------------------------------------------
__global__ void proj_kernel(const float* __restrict__ y,
                            const float* __restrict__ M) {
    __shared__ float Ms[ET][DHH + 1];   // pad -> bank (e+d)%32, conflict-free
    __shared__ float Ys[BT][DHH];

    const int t = threadIdx.x;
    const int e0 = blockIdx.x * ET;
    const int d0 = blockIdx.y * DHH;
    const int b0 = blockIdx.z * BT;

    if (blockIdx.x == 0 && blockIdx.y == 0 && blockIdx.z == 0 && t < B_)
        g_sums[t] = 0.0f;

    // M tile: 32 rows x 64 -> 8 threads/row, 8 floats each (2 LDG.128)
    {
        const int row = t >> 3;
        const int c0 = (t & 7) * 8;
        const float4* ms = reinterpret_cast<const float4*>(M + (size_t)(e0 + row) * D_ + d0 + c0);
        float4 a = ms[0], b = ms[1];
        Ms[row][c0 + 0] = a.x; Ms[row][c0 + 1] = a.y; Ms[row][c0 + 2] = a.z; Ms[row][c0 + 3] = a.w;
        Ms[row][c0 + 4] = b.x; Ms[row][c0 + 5] = b.y; Ms[row][c0 + 6] = b.z; Ms[row][c0 + 7] = b.w;
    }
    // Y tile: 16 rows x 64 -> 16 threads/row, 1 float4 each
    {
        const int row = t >> 4;
        const int c0 = (t & 15) * 4;
        *reinterpret_cast<float4*>(&Ys[row][c0]) =
            *reinterpret_cast<const float4*>(y + (size_t)(b0 + row) * D_ + d0 + c0);
    }
    __syncthreads();

    const int e  = t & 31;        // = lane
    const int bg = t >> 5;        // warp id (warp-uniform) -> 2 batches

    float acc0 = 0.f, acc1 = 0.f;
#pragma unroll
    for (int dd = 0; dd < DHH; dd += 4) {
        float m0 = Ms[e][dd + 0];
        float m1 = Ms[e][dd + 1];
        float m2 = Ms[e][dd + 2];
        float m3 = Ms[e][dd + 3];
        float4 y0 = *reinterpret_cast<const float4*>(&Ys[bg * 2 + 0][dd]);
        float4 y1 = *reinterpret_cast<const float4*>(&Ys[bg * 2 + 1][dd]);
        acc0 = fmaf(m0, y0.x, acc0); acc0 = fmaf(m1, y0.y, acc0);
        acc0 = fmaf(m2, y0.z, acc0); acc0 = fmaf(m3, y0.w, acc0);
        acc1 = fmaf(m0, y1.x, acc1); acc1 = fmaf(m1, y1.y, acc1);
        acc1 = fmaf(m2, y1.z, acc1); acc1 = fmaf(m3, y1.w, acc1);
    }

    // coalesced spread REDs (e = lane -> 128B contiguous per batch row)
    atomicAdd(&g_proj[b0 + bg * 2 + 0][e0 + e], acc0);
    atomicAdd(&g_proj[b0 + bg * 2 + 1][e0 + e], acc1);
}

// ---------------------------------------------------------------------------
// Kernel 2 (round-8 exact): warp handles TWO consecutive s-rows; masked rows
// skip their x stream; x via __ldcs. grid (S_/16, B_), block 256.
// ---------------------------------------------------------------------------
__global__ void eij_kernel(const float* __restrict__ x,
                           const int* __restrict__ mask,
                           float* __restrict__ out) {
    const int b = blockIdx.y;
    const int warp = threadIdx.x >> 5;
    const int lane = threadIdx.x & 31;
    const int s0 = blockIdx.x * 16 + warp * 2;

    __shared__ float4 sp[D_ / 4];
    __shared__ float warp_partial[8];

    const int mk0 = mask[b * S_ + s0];
    const int mk1 = mask[b * S_ + s0 + 1];

    sp[threadIdx.x] = reinterpret_cast<const float4*>(&g_proj[b][0])[threadIdx.x];
    __syncthreads();

    float d0 = 0.0f, d1 = 0.0f;
    if (mk0 != 0) {
        const float4* xv = reinterpret_cast<const float4*>(x + ((size_t)b * S_ + s0) * D_);
#pragma unroll
        for (int j = 0; j < D_ / 128; ++j) {
            const int idx = j * 32 + lane;
            float4 xa = __ldcs(xv + idx);
            float4 pa = sp[idx];
            d0 = fmaf(xa.x, pa.x, d0);
            d0 = fmaf(xa.y, pa.y, d0);
            d0 = fmaf(xa.z, pa.z, d0);
            d0 = fmaf(xa.w, pa.w, d0);
        }
    }
    if (mk1 != 0) {
        const float4* xv = reinterpret_cast<const float4*>(x + ((size_t)b * S_ + s0 + 1) * D_);
#pragma unroll
        for (int j = 0; j < D_ / 128; ++j) {
            const int idx = j * 32 + lane;
            float4 xa = __ldcs(xv + idx);
            float4 pa = sp[idx];
            d1 = fmaf(xa.x, pa.x, d1);
            d1 = fmaf(xa.y, pa.y, d1);
            d1 = fmaf(xa.z, pa.z, d1);
            d1 = fmaf(xa.w, pa.w, d1);
        }
    }
#pragma unroll
    for (int off = 16; off > 0; off >>= 1) {
        d0 += __shfl_xor_sync(0xFFFFFFFFu, d0, off);
        d1 += __shfl_xor_sync(0xFFFFFFFFu, d1, off);
    }

    float a0 = (mk0 != 0) ? __expf(tanhf(d0)) : 0.0f;
    float a1 = (mk1 != 0) ? __expf(tanhf(d1)) : 0.0f;

    if (lane == 0) {
        reinterpret_cast<float2*>(out)[(b * S_ + s0) >> 1] = make_float2(a0, a1);
        warp_partial[warp] = a0 + a1;
    }
    __syncthreads();

    if (threadIdx.x < 8) {
        float v = warp_partial[threadIdx.x];
#pragma unroll
        for (int off = 4; off > 0; off >>= 1)
            v += __shfl_xor_sync(0x000000FFu, v, off);
        if (threadIdx.x == 0) atomicAdd(&g_sums[b], v);
    }
}

// ---------------------------------------------------------------------------
// Kernel 3: out /= (sum + EPS) via float4; zero g_proj for next replay.
// ---------------------------------------------------------------------------
__global__ void norm_kernel(float* __restrict__ out) {
    const int i = blockIdx.x * blockDim.x + threadIdx.x;   // 0..16383
    const int b = i / (S_ / 4);
    float inv = 1.0f / (g_sums[b] + EPS);
    float4 v = reinterpret_cast<float4*>(out)[i];
    v.x *= inv; v.y *= inv; v.z *= inv; v.w *= inv;
    reinterpret_cast<float4*>(out)[i] = v;
    if (i < B_ * D_ / 4)
        reinterpret_cast<float4*>(g_proj)[i] = make_float4(0.f, 0.f, 0.f, 0.f);
}

extern "C" void kernel_launch(void* const* d_in, const int* in_sizes, int n_in,
                              void* d_out, int out_size) {
    const float* x    = (const float*)d_in[0];   // [32, 2048, 1024]
    const float* y    = (const float*)d_in[1];   // [32, 1024]
    const int*   mask = (const int*)d_in[2];     // [32, 2048]
    const float* M    = (const float*)d_in[3];   // [1024, 1024]
    float* out = (float*)d_out;                  // [32, 2048]

    dim3 g1(D_ / ET, KS, B_ / BT);
    proj_kernel<<<g1, 256>>>(y, M);
    dim3 g2(S_ / 16, B_);
    eij_kernel<<<g2, 256>>>(x, mask, out);
    norm_kernel<<<(B_ * S_ / 4) / 256, 256>>>(out);
}

// round 15
// speedup vs baseline: 1.3154x; 1.3154x over previous
#include <cuda_runtime.h>
#include <math.h>

#define EPS 1e-7f

// B=32, S=2048, D=1024
#define B_ 32
#define S_ 2048
#define D_ 1024

#define KSPLIT 8              // proj split-K factor
#define DH (D_ / KSPLIT)      // 128 d-elements per slice
#define BPW2 4                // batches per warp (y tile in regs)
#define EPW 8                 // e-rows per warp (M streamed)

__device__ float g_proj[B_][D_];   // merged proj (atomicAdd; zeroed by norm for next replay)
__device__ float g_sums[B_];       // per-batch sum of a

// ---------------------------------------------------------------------------
// Kernel 1 (round-8 config + 1-deep M prefetch pipeline):
// grid (16, 8, 8) = 1024 blocks, 256 thr (8 warps). Warp: 32 dots (8e x 4b)
// over a 128-d slice; log-tree multi-value reduction (31 SHFL) leaves dot l
// on lane l (acc[ee*4+bb]); spread-address RED.ADD per lane.
// ---------------------------------------------------------------------------
__global__ void proj_kernel(const float* __restrict__ y,
                            const float* __restrict__ M) {
    if (blockIdx.x == 0 && blockIdx.y == 0 && blockIdx.z == 0 && threadIdx.x < B_)
        g_sums[threadIdx.x] = 0.0f;

    const int warp = threadIdx.x >> 5;
    const int lane = threadIdx.x & 31;
    const int e0 = (blockIdx.x * 8 + warp) * EPW;
    const int b0 = blockIdx.y * BPW2;
    const int h  = blockIdx.z;

    // y tile: 4 batches x 128-d slice, 1 float4 per lane per batch
    float4 yr[BPW2];
#pragma unroll
    for (int bb = 0; bb < BPW2; ++bb) {
        const float4* yv = reinterpret_cast<const float4*>(
            y + (size_t)(b0 + bb) * D_) + h * (DH / 4);
        yr[bb] = yv[lane];
    }

    const float4* Mv0 = reinterpret_cast<const float4*>(M + (size_t)e0 * D_) + h * (DH / 4);

    float acc[32];   // acc[ee*4+bb]
    float4 m = Mv0[lane];                       // prefetch ee=0
#pragma unroll
    for (int ee = 0; ee < EPW; ++ee) {
        float4 mn;
        if (ee + 1 < EPW) {
            const float4* Mv = reinterpret_cast<const float4*>(
                M + (size_t)(e0 + ee + 1) * D_) + h * (DH / 4);
            mn = Mv[lane];                      // load next row during FMAs
        }
#pragma unroll
        for (int bb = 0; bb < BPW2; ++bb) {
            float a = 0.0f;
            a = fmaf(m.x, yr[bb].x, a);
            a = fmaf(m.y, yr[bb].y, a);
            a = fmaf(m.z, yr[bb].z, a);
            a = fmaf(m.w, yr[bb].w, a);
            acc[ee * 4 + bb] = a;
        }
        if (ee + 1 < EPW) m = mn;
    }

    // multi-value tree reduction: 32 values x 32 lanes -> value v==lane on lane
#pragma unroll
    for (int off = 16; off > 0; off >>= 1) {
#pragma unroll
        for (int j = 0; j < off; ++j) {
            float send = (lane & off) ? acc[j] : acc[j + off];
            float other = __shfl_xor_sync(0xFFFFFFFFu, send, off);
            acc[j] = ((lane & off) ? acc[j + off] : acc[j]) + other;
        }
    }
    // v = ee*4+bb == lane  ->  bb = lane&3, ee = lane>>2
    atomicAdd(&g_proj[b0 + (lane & 3)][e0 + (lane >> 2)], acc[0]);
}

// ---------------------------------------------------------------------------
// Kernel 2 (round-8 exact): warp handles TWO consecutive s-rows; masked rows
// skip their x stream; x via __ldcs. grid (S_/16, B_), block 256.
// ---------------------------------------------------------------------------
__global__ void eij_kernel(const float* __restrict__ x,
                           const int* __restrict__ mask,
                           float* __restrict__ out) {
    const int b = blockIdx.y;
    const int warp = threadIdx.x >> 5;
    const int lane = threadIdx.x & 31;
    const int s0 = blockIdx.x * 16 + warp * 2;

    __shared__ float4 sp[D_ / 4];
    __shared__ float warp_partial[8];

    const int mk0 = mask[b * S_ + s0];
    const int mk1 = mask[b * S_ + s0 + 1];

    sp[threadIdx.x] = reinterpret_cast<const float4*>(&g_proj[b][0])[threadIdx.x];
    __syncthreads();

    float d0 = 0.0f, d1 = 0.0f;
    if (mk0 != 0) {
        const float4* xv = reinterpret_cast<const float4*>(x + ((size_t)b * S_ + s0) * D_);
#pragma unroll
        for (int j = 0; j < D_ / 128; ++j) {
            const int idx = j * 32 + lane;
            float4 xa = __ldcs(xv + idx);
            float4 pa = sp[idx];
            d0 = fmaf(xa.x, pa.x, d0);
            d0 = fmaf(xa.y, pa.y, d0);
            d0 = fmaf(xa.z, pa.z, d0);
            d0 = fmaf(xa.w, pa.w, d0);
        }
    }
    if (mk1 != 0) {
        const float4* xv = reinterpret_cast<const float4*>(x + ((size_t)b * S_ + s0 + 1) * D_);
#pragma unroll
        for (int j = 0; j < D_ / 128; ++j) {
            const int idx = j * 32 + lane;
            float4 xa = __ldcs(xv + idx);
            float4 pa = sp[idx];
            d1 = fmaf(xa.x, pa.x, d1);
            d1 = fmaf(xa.y, pa.y, d1);
            d1 = fmaf(xa.z, pa.z, d1);
            d1 = fmaf(xa.w, pa.w, d1);
        }
    }
#pragma unroll
    for (int off = 16; off > 0; off >>= 1) {
        d0 += __shfl_xor_sync(0xFFFFFFFFu, d0, off);
        d1 += __shfl_xor_sync(0xFFFFFFFFu, d1, off);
    }

    float a0 = (mk0 != 0) ? __expf(tanhf(d0)) : 0.0f;
    float a1 = (mk1 != 0) ? __expf(tanhf(d1)) : 0.0f;

    if (lane == 0) {
        reinterpret_cast<float2*>(out)[(b * S_ + s0) >> 1] = make_float2(a0, a1);
        warp_partial[warp] = a0 + a1;
    }
    __syncthreads();

    if (threadIdx.x < 8) {
        float v = warp_partial[threadIdx.x];
#pragma unroll
        for (int off = 4; off > 0; off >>= 1)
            v += __shfl_xor_sync(0x000000FFu, v, off);
        if (threadIdx.x == 0) atomicAdd(&g_sums[b], v);
    }
}

// ---------------------------------------------------------------------------
// Kernel 3 (round-8 exact): out /= (sum + EPS) via float4; zero g_proj.
// ---------------------------------------------------------------------------
__global__ void norm_kernel(float* __restrict__ out) {
    const int i = blockIdx.x * blockDim.x + threadIdx.x;   // 0..16383
    const int b = i / (S_ / 4);
    float inv = 1.0f / (g_sums[b] + EPS);
    float4 v = reinterpret_cast<float4*>(out)[i];
    v.x *= inv; v.y *= inv; v.z *= inv; v.w *= inv;
    reinterpret_cast<float4*>(out)[i] = v;
    if (i < B_ * D_ / 4)
        reinterpret_cast<float4*>(g_proj)[i] = make_float4(0.f, 0.f, 0.f, 0.f);
}

extern "C" void kernel_launch(void* const* d_in, const int* in_sizes, int n_in,
                              void* d_out, int out_size) {
    const float* x    = (const float*)d_in[0];   // [32, 2048, 1024]
    const float* y    = (const float*)d_in[1];   // [32, 1024]
    const int*   mask = (const int*)d_in[2];     // [32, 2048]
    const float* M    = (const float*)d_in[3];   // [1024, 1024]
    float* out = (float*)d_out;                  // [32, 2048]

    dim3 g1(D_ / (EPW * 8), B_ / BPW2, KSPLIT);
    proj_kernel<<<g1, 256>>>(y, M);
    dim3 g2(S_ / 16, B_);
    eij_kernel<<<g2, 256>>>(x, mask, out);
    norm_kernel<<<(B_ * S_ / 4) / 256, 256>>>(out);
}

// round 16
// speedup vs baseline: 1.3179x; 1.0019x over previous
#include <cuda_runtime.h>
#include <math.h>

#define EPS 1e-7f

// B=32, S=2048, D=1024
#define B_ 32
#define S_ 2048
#define D_ 1024

#define KSPLIT 8              // proj split-K factor
#define DH (D_ / KSPLIT)      // 128 d-elements per slice
#define BPW2 4                // batches per warp (y tile in regs)
#define EPW 8                 // e-rows per warp (M streamed)

__device__ float g_proj[B_][D_];   // merged proj (atomicAdd; zeroed by norm for next replay)
__device__ float g_sums[B_];       // per-batch sum of a

// ---------------------------------------------------------------------------
// Kernel 1 (round-8 proven config): g_proj[b][e] += partial dot over slice h.
// grid (16, 8, 8) = 1024 blocks, 256 thr (8 warps). Warp: 32 dots (8e x 4b)
// over a 128-d slice; log-tree multi-value reduction (31 SHFL) leaves dot l
// on lane l (acc[ee*4+bb]); spread-address RED.ADD per lane.
// ---------------------------------------------------------------------------
__global__ void proj_kernel(const float* __restrict__ y,
                            const float* __restrict__ M) {
    if (blockIdx.x == 0 && blockIdx.y == 0 && blockIdx.z == 0 && threadIdx.x < B_)
        g_sums[threadIdx.x] = 0.0f;

    const int warp = threadIdx.x >> 5;
    const int lane = threadIdx.x & 31;
    const int e0 = (blockIdx.x * 8 + warp) * EPW;
    const int b0 = blockIdx.y * BPW2;
    const int h  = blockIdx.z;

    // y tile: 4 batches x 128-d slice, 1 float4 per lane per batch
    float4 yr[BPW2];
#pragma unroll
    for (int bb = 0; bb < BPW2; ++bb) {
        const float4* yv = reinterpret_cast<const float4*>(
            y + (size_t)(b0 + bb) * D_) + h * (DH / 4);
        yr[bb] = yv[lane];
    }

    float acc[32];   // acc[ee*4+bb]
#pragma unroll
    for (int ee = 0; ee < EPW; ++ee) {
        const float4* Mv = reinterpret_cast<const float4*>(
            M + (size_t)(e0 + ee) * D_) + h * (DH / 4);
        float4 m = Mv[lane];
#pragma unroll
        for (int bb = 0; bb < BPW2; ++bb) {
            float a = 0.0f;
            a = fmaf(m.x, yr[bb].x, a);
            a = fmaf(m.y, yr[bb].y, a);
            a = fmaf(m.z, yr[bb].z, a);
            a = fmaf(m.w, yr[bb].w, a);
            acc[ee * 4 + bb] = a;
        }
    }

    // multi-value tree reduction: 32 values x 32 lanes -> value v==lane on lane
#pragma unroll
    for (int off = 16; off > 0; off >>= 1) {
#pragma unroll
        for (int j = 0; j < off; ++j) {
            float send = (lane & off) ? acc[j] : acc[j + off];
            float other = __shfl_xor_sync(0xFFFFFFFFu, send, off);
            acc[j] = ((lane & off) ? acc[j + off] : acc[j]) + other;
        }
    }
    // v = ee*4+bb == lane  ->  bb = lane&3, ee = lane>>2
    atomicAdd(&g_proj[b0 + (lane & 3)][e0 + (lane >> 2)], acc[0]);
}

// ---------------------------------------------------------------------------
// Kernel 2 (PDL + full x register prefetch): warp handles TWO consecutive
// s-rows. PRE-SYNC: mask loads + both rows' x (independent of proj) stream
// into registers, overlapping proj's execution. POST-SYNC: stage proj, FMA
// from registers. grid (S_/16, B_), block 256.
// ---------------------------------------------------------------------------
__global__ void eij_kernel(const float* __restrict__ x,
                           const int* __restrict__ mask,
                           float* __restrict__ out) {
    const int b = blockIdx.y;
    const int warp = threadIdx.x >> 5;
    const int lane = threadIdx.x & 31;
    const int s0 = blockIdx.x * 16 + warp * 2;

    __shared__ float4 sp[D_ / 4];
    __shared__ float warp_partial[8];

    // ---- pre-sync phase: everything independent of proj ----
    const int mk0 = mask[b * S_ + s0];
    const int mk1 = mask[b * S_ + s0 + 1];

    float4 xr0[8], xr1[8];
    if (mk0 != 0) {
        const float4* xv = reinterpret_cast<const float4*>(x + ((size_t)b * S_ + s0) * D_);
#pragma unroll
        for (int j = 0; j < 8; ++j) xr0[j] = __ldcs(xv + j * 32 + lane);
    }
    if (mk1 != 0) {
        const float4* xv = reinterpret_cast<const float4*>(x + ((size_t)b * S_ + s0 + 1) * D_);
#pragma unroll
        for (int j = 0; j < 8; ++j) xr1[j] = __ldcs(xv + j * 32 + lane);
    }

    cudaGridDependencySynchronize();   // proj RED.ADDs visible after this

    // ---- post-sync: stage proj, compute from registers ----
    sp[threadIdx.x] = reinterpret_cast<const float4*>(&g_proj[b][0])[threadIdx.x];
    __syncthreads();

    float d0 = 0.0f, d1 = 0.0f;
    if (mk0 != 0) {
#pragma unroll
        for (int j = 0; j < 8; ++j) {
            float4 pa = sp[j * 32 + lane];
            d0 = fmaf(xr0[j].x, pa.x, d0);
            d0 = fmaf(xr0[j].y, pa.y, d0);
            d0 = fmaf(xr0[j].z, pa.z, d0);
            d0 = fmaf(xr0[j].w, pa.w, d0);
        }
    }
    if (mk1 != 0) {
#pragma unroll
        for (int j = 0; j < 8; ++j) {
            float4 pa = sp[j * 32 + lane];
            d1 = fmaf(xr1[j].x, pa.x, d1);
            d1 = fmaf(xr1[j].y, pa.y, d1);
            d1 = fmaf(xr1[j].z, pa.z, d1);
            d1 = fmaf(xr1[j].w, pa.w, d1);
        }
    }
#pragma unroll
    for (int off = 16; off > 0; off >>= 1) {
        d0 += __shfl_xor_sync(0xFFFFFFFFu, d0, off);
        d1 += __shfl_xor_sync(0xFFFFFFFFu, d1, off);
    }

    float a0 = (mk0 != 0) ? __expf(tanhf(d0)) : 0.0f;
    float a1 = (mk1 != 0) ? __expf(tanhf(d1)) : 0.0f;

    if (lane == 0) {
        reinterpret_cast<float2*>(out)[(b * S_ + s0) >> 1] = make_float2(a0, a1);
        warp_partial[warp] = a0 + a1;
    }
    __syncthreads();

    if (threadIdx.x < 8) {
        float v = warp_partial[threadIdx.x];
#pragma unroll
        for (int off = 4; off > 0; off >>= 1)
            v += __shfl_xor_sync(0x000000FFu, v, off);
        if (threadIdx.x == 0) atomicAdd(&g_sums[b], v);
    }
}

// ---------------------------------------------------------------------------
// Kernel 3: out /= (sum + EPS) via float4; zero g_proj for next replay.
// ---------------------------------------------------------------------------
__global__ void norm_kernel(float* __restrict__ out) {
    const int i = blockIdx.x * blockDim.x + threadIdx.x;   // 0..16383
    const int b = i / (S_ / 4);
    float inv = 1.0f / (g_sums[b] + EPS);
    float4 v = reinterpret_cast<float4*>(out)[i];
    v.x *= inv; v.y *= inv; v.z *= inv; v.w *= inv;
    reinterpret_cast<float4*>(out)[i] = v;
    if (i < B_ * D_ / 4)
        reinterpret_cast<float4*>(g_proj)[i] = make_float4(0.f, 0.f, 0.f, 0.f);
}

extern "C" void kernel_launch(void* const* d_in, const int* in_sizes, int n_in,
                              void* d_out, int out_size) {
    const float* x    = (const float*)d_in[0];   // [32, 2048, 1024]
    const float* y    = (const float*)d_in[1];   // [32, 1024]
    const int*   mask = (const int*)d_in[2];     // [32, 2048]
    const float* M    = (const float*)d_in[3];   // [1024, 1024]
    float* out = (float*)d_out;                  // [32, 2048]

    dim3 g1(D_ / (EPW * 8), B_ / BPW2, KSPLIT);
    proj_kernel<<<g1, 256>>>(y, M);

    // eij: PDL launch — pre-sync phase streams x while proj finishes
    cudaLaunchAttribute attr[1];
    attr[0].id = cudaLaunchAttributeProgrammaticStreamSerialization;
    attr[0].val.programmaticStreamSerializationAllowed = 1;
    cudaLaunchConfig_t cfg = {};
    cfg.gridDim = dim3(S_ / 16, B_, 1);
    cfg.blockDim = dim3(256, 1, 1);
    cfg.stream = 0;
    cfg.attrs = attr;
    cfg.numAttrs = 1;
    cudaLaunchKernelEx(&cfg, eij_kernel, x, mask, out);

    norm_kernel<<<(B_ * S_ / 4) / 256, 256>>>(out);
}